// round 1
// baseline (speedup 1.0000x reference)
#include <cuda_runtime.h>
#include <cstdint>

#define N_NODES 50000
#define N_EDGES 400000
#define F_IN    256
#define HID     1024
#define F_MID   512
#define N_OUT   10
#define EPS_BN  1e-5f

// ---------------- scratch (device globals; no allocations allowed) ----------
__device__ float g_agg[(size_t)N_NODES * HID];   // aggregate buffer (layer1 uses first N*256)
__device__ float g_tmp[(size_t)N_NODES * HID];   // pre-BN sage output / fc output
__device__ float g_h  [(size_t)N_NODES * HID];   // post BN+ReLU activations
__device__ int   g_deg[N_NODES];
__device__ int   g_off[N_NODES];
__device__ int   g_cur[N_NODES];
__device__ int   g_csr[N_EDGES];
__device__ float g_sum[HID];
__device__ float g_sumsq[HID];
__device__ float g_a[HID];
__device__ float g_c[HID];
__device__ int   g_is64;

// ---------------- dtype detection for edge_index (int64 vs int32) ----------
__global__ void k_detect(const unsigned int* e) {
    if (threadIdx.x == 0) {
        int is64 = 1;
        for (int i = 0; i < 64; i++) {
            if (e[2 * i + 1] != 0u) { is64 = 0; break; }
        }
        g_is64 = is64;
    }
}

__device__ __forceinline__ int load_edge(const void* edges, int idx) {
    if (g_is64) return (int)((const long long*)edges)[idx];
    return ((const int*)edges)[idx];
}

// ---------------- CSR build ----------------
__global__ void k_hist(const void* edges) {
    int i = blockIdx.x * blockDim.x + threadIdx.x;
    if (i < N_EDGES) {
        int dst = load_edge(edges, N_EDGES + i);
        atomicAdd(&g_deg[dst], 1);
    }
}

__global__ void k_scan() {
    __shared__ int sh[1024];
    __shared__ int carry;
    int t = threadIdx.x;
    if (t == 0) carry = 0;
    __syncthreads();
    for (int base = 0; base < N_NODES; base += 1024) {
        int v = (base + t < N_NODES) ? g_deg[base + t] : 0;
        sh[t] = v;
        __syncthreads();
        #pragma unroll
        for (int off = 1; off < 1024; off <<= 1) {
            int add = (t >= off) ? sh[t - off] : 0;
            __syncthreads();
            sh[t] += add;
            __syncthreads();
        }
        int excl = sh[t] - v;
        int c0 = carry;
        if (base + t < N_NODES) {
            g_off[base + t] = c0 + excl;
            g_cur[base + t] = c0 + excl;
        }
        __syncthreads();
        if (t == 0) carry = c0 + sh[1023];
        __syncthreads();
    }
}

__global__ void k_scatter(const void* edges) {
    int i = blockIdx.x * blockDim.x + threadIdx.x;
    if (i < N_EDGES) {
        int src = load_edge(edges, i);
        int dst = load_edge(edges, N_EDGES + i);
        int p = atomicAdd(&g_cur[dst], 1);
        g_csr[p] = src;
    }
}

// ---------------- mean aggregation (atomic-free gather) ----------------
template <int F>
__global__ void k_aggregate(const float* __restrict__ X, float* __restrict__ AGG) {
    int node = blockIdx.x;
    int t = threadIdx.x;           // 128 threads
    constexpr int J = F / 128;
    float acc[J];
    #pragma unroll
    for (int j = 0; j < J; j++) acc[j] = 0.0f;

    int start = g_off[node];
    int deg = g_deg[node];
    for (int i = 0; i < deg; i++) {
        const float* row = X + (size_t)g_csr[start + i] * F;
        #pragma unroll
        for (int j = 0; j < J; j++) acc[j] += row[t + j * 128];
    }
    float inv = (deg > 0) ? (1.0f / (float)deg) : 0.0f;
    float* o = AGG + (size_t)node * F;
    #pragma unroll
    for (int j = 0; j < J; j++) o[t + j * 128] = acc[j] * inv;
}

// ---------------- SGEMM: C = A1@W1 (+ A2@W2) + bias (+ReLU) ----------------
// 128x128 block tile, BK=16, 256 threads, 8x8 per thread.
template <bool DUAL, bool RELU>
__global__ __launch_bounds__(256, 2) void k_sgemm(
    const float* __restrict__ A1, const float* __restrict__ W1,
    const float* __restrict__ A2, const float* __restrict__ W2,
    const float* __restrict__ bias, float* __restrict__ C,
    int M, int N, int K)
{
    __shared__ float As[16][128];
    __shared__ float Bs[16][128];
    int tid = threadIdx.x;
    int rowBase = blockIdx.y * 128;
    int colBase = blockIdx.x * 128;
    int tr = tid / 16;   // 0..15
    int tc = tid % 16;   // 0..15

    float acc[8][8];
    #pragma unroll
    for (int m = 0; m < 8; m++)
        #pragma unroll
        for (int n = 0; n < 8; n++) acc[m][n] = 0.0f;

    const int passes = DUAL ? 2 : 1;
    for (int pass = 0; pass < passes; ++pass) {
        const float* A = pass ? A2 : A1;
        const float* W = pass ? W2 : W1;
        for (int k0 = 0; k0 < K; k0 += 16) {
            // A tile: 128 rows x 16 k (512 float4, 2 per thread), store transposed
            #pragma unroll
            for (int i = 0; i < 2; i++) {
                int idx = tid * 2 + i;            // 0..511
                int ar = idx >> 2;                // 0..127
                int ac = (idx & 3) * 4;           // 0,4,8,12
                float4 v = make_float4(0.f, 0.f, 0.f, 0.f);
                int gr = rowBase + ar;
                if (gr < M) v = *(const float4*)(A + (size_t)gr * K + (k0 + ac));
                As[ac + 0][ar] = v.x;
                As[ac + 1][ar] = v.y;
                As[ac + 2][ar] = v.z;
                As[ac + 3][ar] = v.w;
            }
            // W tile: 16 k-rows x 128 cols (512 float4, 2 per thread)
            #pragma unroll
            for (int i = 0; i < 2; i++) {
                int idx = tid * 2 + i;
                int wr = idx >> 5;                // 0..15
                int wc = (idx & 31) * 4;          // 0..124
                float4 v = *(const float4*)(W + (size_t)(k0 + wr) * N + (colBase + wc));
                *(float4*)&Bs[wr][wc] = v;
            }
            __syncthreads();
            #pragma unroll
            for (int k = 0; k < 16; k++) {
                float ra[8], rb[8];
                #pragma unroll
                for (int m = 0; m < 4; m++) {
                    float4 v = *(const float4*)&As[k][tr * 8 + m * 4];
                    ra[m * 4 + 0] = v.x; ra[m * 4 + 1] = v.y;
                    ra[m * 4 + 2] = v.z; ra[m * 4 + 3] = v.w;
                }
                #pragma unroll
                for (int n = 0; n < 4; n++) {
                    float4 v = *(const float4*)&Bs[k][tc * 8 + n * 4];
                    rb[n * 4 + 0] = v.x; rb[n * 4 + 1] = v.y;
                    rb[n * 4 + 2] = v.z; rb[n * 4 + 3] = v.w;
                }
                #pragma unroll
                for (int m = 0; m < 8; m++)
                    #pragma unroll
                    for (int n = 0; n < 8; n++)
                        acc[m][n] += ra[m] * rb[n];
            }
            __syncthreads();
        }
    }

    // epilogue
    #pragma unroll
    for (int m = 0; m < 8; m++) {
        int gr = rowBase + tr * 8 + m;
        if (gr < M) {
            #pragma unroll
            for (int n = 0; n < 8; n += 4) {
                int gc = colBase + tc * 8 + n;
                float4 v;
                v.x = acc[m][n + 0] + bias[gc + 0];
                v.y = acc[m][n + 1] + bias[gc + 1];
                v.z = acc[m][n + 2] + bias[gc + 2];
                v.w = acc[m][n + 3] + bias[gc + 3];
                if (RELU) {
                    v.x = fmaxf(v.x, 0.f); v.y = fmaxf(v.y, 0.f);
                    v.z = fmaxf(v.z, 0.f); v.w = fmaxf(v.w, 0.f);
                }
                *(float4*)(C + (size_t)gr * N + gc) = v;
            }
        }
    }
}

// ---------------- BN column stats (C fixed at HID=1024) ----------------
__global__ void k_colstats(const float* __restrict__ X) {
    int t = threadIdx.x;  // 256
    int stripe = blockIdx.x;
    int rows_per = (N_NODES + gridDim.x - 1) / gridDim.x;
    int r0 = stripe * rows_per;
    int r1 = min(N_NODES, r0 + rows_per);
    float s[4] = {0, 0, 0, 0}, q[4] = {0, 0, 0, 0};
    for (int r = r0; r < r1; r++) {
        const float* row = X + (size_t)r * HID;
        #pragma unroll
        for (int j = 0; j < 4; j++) {
            float v = row[t + j * 256];
            s[j] += v;
            q[j] += v * v;
        }
    }
    #pragma unroll
    for (int j = 0; j < 4; j++) {
        atomicAdd(&g_sum[t + j * 256], s[j]);
        atomicAdd(&g_sumsq[t + j * 256], q[j]);
    }
}

__global__ void k_bnparams(const float* __restrict__ g, const float* __restrict__ be) {
    int c = blockIdx.x * blockDim.x + threadIdx.x;
    if (c < HID) {
        float m = g_sum[c] * (1.0f / N_NODES);
        float var = g_sumsq[c] * (1.0f / N_NODES) - m * m;
        float a = g[c] * rsqrtf(var + EPS_BN);
        g_a[c] = a;
        g_c[c] = be[c] - m * a;
    }
}

__global__ void k_bnrelu(const float* __restrict__ X, float* __restrict__ Y) {
    size_t i = (size_t)blockIdx.x * blockDim.x + threadIdx.x;  // float4 index
    const size_t total = (size_t)N_NODES * HID / 4;
    if (i < total) {
        int c = (int)((i * 4) % HID);
        float4 v = ((const float4*)X)[i];
        v.x = fmaxf(0.f, v.x * g_a[c + 0] + g_c[c + 0]);
        v.y = fmaxf(0.f, v.y * g_a[c + 1] + g_c[c + 1]);
        v.z = fmaxf(0.f, v.z * g_a[c + 2] + g_c[c + 2]);
        v.w = fmaxf(0.f, v.w * g_a[c + 3] + g_c[c + 3]);
        ((float4*)Y)[i] = v;
    }
}

// ---------------- final head: out = H@Wo + bo, N=10 (warp per row) ----------
__global__ void k_out(const float* __restrict__ H, const float* __restrict__ Wo,
                      const float* __restrict__ bo, float* __restrict__ Out) {
    __shared__ float sw[F_MID * N_OUT];  // 20KB
    for (int i = threadIdx.x; i < F_MID * N_OUT; i += blockDim.x) sw[i] = Wo[i];
    __syncthreads();
    int warp = threadIdx.x / 32, lane = threadIdx.x % 32;
    int row = blockIdx.x * (blockDim.x / 32) + warp;
    if (row >= N_NODES) return;
    float acc[N_OUT];
    #pragma unroll
    for (int o = 0; o < N_OUT; o++) acc[o] = 0.0f;
    const float* h = H + (size_t)row * F_MID;
    for (int k = lane; k < F_MID; k += 32) {
        float hv = h[k];
        #pragma unroll
        for (int o = 0; o < N_OUT; o++) acc[o] += hv * sw[k * N_OUT + o];
    }
    #pragma unroll
    for (int o = 0; o < N_OUT; o++) {
        #pragma unroll
        for (int off = 16; off; off >>= 1)
            acc[o] += __shfl_down_sync(0xffffffffu, acc[o], off);
    }
    if (lane == 0) {
        #pragma unroll
        for (int o = 0; o < N_OUT; o++)
            Out[(size_t)row * N_OUT + o] = acc[o] + bo[o];
    }
}

// ---------------- launch ----------------
extern "C" void kernel_launch(void* const* d_in, const int* in_sizes, int n_in,
                              void* d_out, int out_size) {
    const float* x   = (const float*)d_in[0];
    const void*  edges = d_in[1];
    const float* W1l = (const float*)d_in[2];
    const float* b1  = (const float*)d_in[3];
    const float* W1r = (const float*)d_in[4];
    const float* g1  = (const float*)d_in[5];
    const float* be1 = (const float*)d_in[6];
    const float* W2l = (const float*)d_in[7];
    const float* b2  = (const float*)d_in[8];
    const float* W2r = (const float*)d_in[9];
    const float* g2  = (const float*)d_in[10];
    const float* be2 = (const float*)d_in[11];
    const float* Wf  = (const float*)d_in[12];
    const float* bf  = (const float*)d_in[13];
    const float* Wo  = (const float*)d_in[14];
    const float* bo  = (const float*)d_in[15];
    float* out = (float*)d_out;

    void *p_deg, *p_sum, *p_sumsq, *p_agg, *p_tmp, *p_h;
    cudaGetSymbolAddress(&p_deg, g_deg);
    cudaGetSymbolAddress(&p_sum, g_sum);
    cudaGetSymbolAddress(&p_sumsq, g_sumsq);
    cudaGetSymbolAddress(&p_agg, g_agg);
    cudaGetSymbolAddress(&p_tmp, g_tmp);
    cudaGetSymbolAddress(&p_h, g_h);
    float* agg = (float*)p_agg;
    float* tmp = (float*)p_tmp;
    float* h   = (float*)p_h;

    // CSR build (once; reused by both layers)
    cudaMemsetAsync(p_deg, 0, N_NODES * sizeof(int));
    k_detect<<<1, 32>>>((const unsigned int*)edges);
    k_hist<<<(N_EDGES + 255) / 256, 256>>>(edges);
    k_scan<<<1, 1024>>>();
    k_scatter<<<(N_EDGES + 255) / 256, 256>>>(edges);

    dim3 gHID(HID / 128, (N_NODES + 127) / 128);
    dim3 gMID(F_MID / 128, (N_NODES + 127) / 128);

    // ---- layer 1 ----
    k_aggregate<F_IN><<<N_NODES, 128>>>(x, agg);
    k_sgemm<true, false><<<gHID, 256>>>(agg, W1l, x, W1r, b1, tmp, N_NODES, HID, F_IN);
    cudaMemsetAsync(p_sum, 0, HID * sizeof(float));
    cudaMemsetAsync(p_sumsq, 0, HID * sizeof(float));
    k_colstats<<<128, 256>>>(tmp);
    k_bnparams<<<HID / 256, 256>>>(g1, be1);
    {
        size_t n4 = (size_t)N_NODES * HID / 4;
        k_bnrelu<<<(unsigned)((n4 + 255) / 256), 256>>>(tmp, h);
    }

    // ---- layer 2 ----
    k_aggregate<HID><<<N_NODES, 128>>>(h, agg);
    k_sgemm<true, false><<<gHID, 256>>>(agg, W2l, h, W2r, b2, tmp, N_NODES, HID, HID);
    cudaMemsetAsync(p_sum, 0, HID * sizeof(float));
    cudaMemsetAsync(p_sumsq, 0, HID * sizeof(float));
    k_colstats<<<128, 256>>>(tmp);
    k_bnparams<<<HID / 256, 256>>>(g2, be2);
    {
        size_t n4 = (size_t)N_NODES * HID / 4;
        k_bnrelu<<<(unsigned)((n4 + 255) / 256), 256>>>(tmp, h);
    }

    // ---- fc + ReLU ----
    k_sgemm<false, true><<<gMID, 256>>>(h, Wf, nullptr, nullptr, bf, tmp, N_NODES, F_MID, HID);

    // ---- head ----
    k_out<<<(N_NODES + 7) / 8, 256>>>(tmp, Wo, bo, out);
}

// round 3
// speedup vs baseline: 2.8754x; 2.8754x over previous
#include <cuda_runtime.h>
#include <cuda_bf16.h>
#include <cstdint>

#define N_NODES 50000
#define N_EDGES 400000
#define F_IN    256
#define HID     1024
#define F_MID   512
#define N_OUT   10
#define EPS_BN  1e-5f

#if defined(__CUDA_ARCH_FEAT_SM103_ALL) || defined(__CUDA_ARCH_FEAT_SM100_ALL) || defined(__CUDA_ARCH_FEAT_SM101_ALL)
#define USE_TC 1
#else
#define USE_TC 0
#endif

// ---------------- scratch (device globals) ----------------
__device__ float g_tmp[(size_t)N_NODES * HID];
__device__ float g_h  [(size_t)N_NODES * HID];
__device__ __nv_bfloat16 g_Ah[(size_t)N_NODES * HID];
__device__ __nv_bfloat16 g_Al[(size_t)N_NODES * HID];
__device__ __nv_bfloat16 g_Bh[(size_t)N_NODES * HID];
__device__ __nv_bfloat16 g_Bl[(size_t)N_NODES * HID];
#define OFF_W1L 0
#define OFF_W1R 262144
#define OFF_W2L 524288
#define OFF_W2R 1572864
#define OFF_WF  2621440
__device__ __nv_bfloat16 g_Wh[3145728];
__device__ __nv_bfloat16 g_Wl[3145728];

__device__ int   g_deg[N_NODES];
__device__ int   g_off[N_NODES];
__device__ int   g_cur[N_NODES];
__device__ int   g_csr[N_EDGES];
__device__ float g_sum[HID];
__device__ float g_sumsq[HID];
__device__ float g_a[HID];
__device__ float g_c[HID];
__device__ int   g_is64;

// ---------------- dtype detection ----------------
__global__ void k_detect(const unsigned int* e) {
    if (threadIdx.x == 0) {
        int is64 = 1;
        for (int i = 0; i < 64; i++)
            if (e[2 * i + 1] != 0u) { is64 = 0; break; }
        g_is64 = is64;
    }
}
__device__ __forceinline__ int load_edge(const void* edges, int idx) {
    if (g_is64) return (int)((const long long*)edges)[idx];
    return ((const int*)edges)[idx];
}

// ---------------- CSR build ----------------
__global__ void k_hist(const void* edges) {
    int i = blockIdx.x * blockDim.x + threadIdx.x;
    if (i < N_EDGES) atomicAdd(&g_deg[load_edge(edges, N_EDGES + i)], 1);
}
__global__ void k_scan() {
    __shared__ int sh[1024];
    __shared__ int carry;
    int t = threadIdx.x;
    if (t == 0) carry = 0;
    __syncthreads();
    for (int base = 0; base < N_NODES; base += 1024) {
        int v = (base + t < N_NODES) ? g_deg[base + t] : 0;
        sh[t] = v;
        __syncthreads();
        #pragma unroll
        for (int off = 1; off < 1024; off <<= 1) {
            int add = (t >= off) ? sh[t - off] : 0;
            __syncthreads();
            sh[t] += add;
            __syncthreads();
        }
        int excl = sh[t] - v;
        int c0 = carry;
        if (base + t < N_NODES) { g_off[base + t] = c0 + excl; g_cur[base + t] = c0 + excl; }
        __syncthreads();
        if (t == 0) carry = c0 + sh[1023];
        __syncthreads();
    }
}
__global__ void k_scatter(const void* edges) {
    int i = blockIdx.x * blockDim.x + threadIdx.x;
    if (i < N_EDGES) {
        int src = load_edge(edges, i);
        int dst = load_edge(edges, N_EDGES + i);
        g_csr[atomicAdd(&g_cur[dst], 1)] = src;
    }
}

// ---------------- mean aggregation -> bf16 hi/lo ----------------
template <int F>
__global__ void k_aggregate(const float* __restrict__ X,
                            __nv_bfloat16* __restrict__ OH, __nv_bfloat16* __restrict__ OL) {
    int node = blockIdx.x;
    int t = threadIdx.x;                 // 128
    constexpr int J = F / 128;
    float acc[J];
    #pragma unroll
    for (int j = 0; j < J; j++) acc[j] = 0.0f;
    int start = g_off[node];
    int deg = g_deg[node];
    for (int i = 0; i < deg; i++) {
        const float* row = X + (size_t)g_csr[start + i] * F;
        #pragma unroll
        for (int j = 0; j < J; j++) acc[j] += row[t + j * 128];
    }
    float inv = (deg > 0) ? (1.0f / (float)deg) : 0.0f;
    size_t o = (size_t)node * F + t;
    #pragma unroll
    for (int j = 0; j < J; j++) {
        float v = acc[j] * inv;
        __nv_bfloat16 h = __float2bfloat16(v);
        OH[o + j * 128] = h;
        OL[o + j * 128] = __float2bfloat16(v - __bfloat162float(h));
    }
}

// ---------------- fp32 -> bf16 hi/lo split ----------------
__global__ void k_split(const float* __restrict__ X, __nv_bfloat16* __restrict__ H,
                        __nv_bfloat16* __restrict__ L, size_t n) {
    size_t i = (size_t)blockIdx.x * blockDim.x + threadIdx.x;
    if (i < n) {
        float v = X[i];
        __nv_bfloat16 h = __float2bfloat16(v);
        H[i] = h;
        L[i] = __float2bfloat16(v - __bfloat162float(h));
    }
}

// ---------------- weight transpose + split ----------------
__global__ void k_wt(const float* __restrict__ W, __nv_bfloat16* __restrict__ Th,
                     __nv_bfloat16* __restrict__ Tl, int K, int N) {
    __shared__ float t[32][33];
    int kb = blockIdx.x * 32, nb = blockIdx.y * 32;
    int tx = threadIdx.x, ty = threadIdx.y;  // 32 x 8
    #pragma unroll
    for (int i = 0; i < 32; i += 8)
        t[ty + i][tx] = W[(size_t)(kb + ty + i) * N + nb + tx];
    __syncthreads();
    #pragma unroll
    for (int i = 0; i < 32; i += 8) {
        float v = t[tx][ty + i];
        size_t o = (size_t)(nb + ty + i) * K + kb + tx;
        __nv_bfloat16 h = __float2bfloat16(v);
        Th[o] = h;
        Tl[o] = __float2bfloat16(v - __bfloat162float(h));
    }
}

// ---------------- GEMM: C[M,N] = sum_p A_p @ B_p^T + bias (+ReLU) ----------
// CTA tile 128x128, K-chunk 64 (one SW128 row), 4-stage cp.async pipeline.
// Two compile-time bodies: tcgen05 (sm_103a cubin) / mma.sync bf16 (plain sm_103).
struct GemmParams {
    const __nv_bfloat16* A[6];
    const __nv_bfloat16* B[6];
    int Kw[6];
    int chEnd[6];
    int totalChunks;
    const float* bias;
    float* C;
    int M;
    int Ncols;
    int relu;
};

#define STAGES 4
#define STAGE_BYTES 32768              // 16KB A + 16KB B
#define SMEM_REQ (2048 + STAGES * STAGE_BYTES)

__device__ __forceinline__ uint32_t swz(uint32_t o) { return o ^ ((o >> 3) & 0x70); }

__device__ __forceinline__ void cp16(uint32_t dst, const void* src, bool p) {
    int sz = p ? 16 : 0;
    asm volatile("cp.async.cg.shared.global [%0], [%1], 16, %2;\n"
                 :: "r"(dst), "l"(src), "r"(sz));
}

#if USE_TC
__device__ __forceinline__ void mwait(uint32_t mb, uint32_t ph) {
    uint32_t done;
    asm volatile(
        "{\n\t.reg .pred p;\n\t"
        "mbarrier.try_wait.parity.acquire.cta.shared::cta.b64 p, [%1], %2;\n\t"
        "selp.b32 %0, 1, 0, p;\n\t}"
        : "=r"(done) : "r"(mb), "r"(ph) : "memory");
    if (!done) {
        asm volatile(
            "{\n\t.reg .pred P1;\n\t"
            "WL_%=:\n\t"
            "mbarrier.try_wait.parity.acquire.cta.shared::cta.b64 P1, [%0], %1, 0x989680;\n\t"
            "@P1 bra.uni WD_%=;\n\t"
            "bra.uni WL_%=;\n\t"
            "WD_%=:\n\t}"
            :: "r"(mb), "r"(ph) : "memory");
    }
}

#define LDTM32(r, addr) \
    asm volatile( \
        "tcgen05.ld.sync.aligned.32x32b.x32.b32 " \
        "{%0, %1, %2, %3, %4, %5, %6, %7, " \
        " %8, %9, %10, %11, %12, %13, %14, %15, " \
        " %16, %17, %18, %19, %20, %21, %22, %23, " \
        " %24, %25, %26, %27, %28, %29, %30, %31}, [%32];" \
        : "=r"((r)[0]),  "=r"((r)[1]),  "=r"((r)[2]),  "=r"((r)[3]), \
          "=r"((r)[4]),  "=r"((r)[5]),  "=r"((r)[6]),  "=r"((r)[7]), \
          "=r"((r)[8]),  "=r"((r)[9]),  "=r"((r)[10]), "=r"((r)[11]), \
          "=r"((r)[12]), "=r"((r)[13]), "=r"((r)[14]), "=r"((r)[15]), \
          "=r"((r)[16]), "=r"((r)[17]), "=r"((r)[18]), "=r"((r)[19]), \
          "=r"((r)[20]), "=r"((r)[21]), "=r"((r)[22]), "=r"((r)[23]), \
          "=r"((r)[24]), "=r"((r)[25]), "=r"((r)[26]), "=r"((r)[27]), \
          "=r"((r)[28]), "=r"((r)[29]), "=r"((r)[30]), "=r"((r)[31]) \
        : "r"(addr))
#endif

__global__ __launch_bounds__(256, 1) void k_gemm(const __grid_constant__ GemmParams P) {
    extern __shared__ char dsm[];
    uint32_t raw;
    asm("{ .reg .u64 t; cvta.to.shared.u64 t, %1; cvt.u32.u64 %0, t; }" : "=r"(raw) : "l"(dsm));
    uint32_t base  = (raw + 1023) & ~1023u;
    uint32_t tiles = base + 1024;
    int tid = threadIdx.x;
    int wid = tid >> 5;
    int lane = tid & 31;
    int mBase = blockIdx.x * 128;
    int nBase = blockIdx.y * 128;

    auto load_chunk = [&](int c, int s) {
        int p = 0;
        while (c >= P.chEnd[p]) p++;
        int c0 = (p ? c - P.chEnd[p - 1] : c) * 64;
        const char* Ab = (const char*)P.A[p] + (size_t)c0 * 2;
        const char* Bb = (const char*)P.B[p] + (size_t)c0 * 2;
        size_t rowB = (size_t)P.Kw[p] * 2;
        uint32_t stA = tiles + s * STAGE_BYTES;
        uint32_t stB = stA + 16384;
        #pragma unroll
        for (int i = 0; i < 4; i++) {
            int o = tid + i * 256;
            int row = o >> 3, kb = (o & 7) * 16;
            bool ok = (mBase + row) < P.M;
            cp16(stA + swz(row * 128 + kb), Ab + (size_t)(mBase + row) * rowB + kb, ok);
        }
        #pragma unroll
        for (int i = 0; i < 4; i++) {
            int o = tid + i * 256;
            int row = o >> 3, kb = (o & 7) * 16;
            cp16(stB + swz(row * 128 + kb), Bb + (size_t)(nBase + row) * rowB + kb, true);
        }
        asm volatile("cp.async.commit_group;" ::: "memory");
    };

    const int T = P.totalChunks;

#if USE_TC
    // ================= tcgen05 path =================
    uint32_t mbar0 = base;
    uint32_t tslot = base + 64;
    if (tid == 0) {
        for (int s = 0; s < STAGES; s++)
            asm volatile("mbarrier.init.shared.b64 [%0], 1;" :: "r"(mbar0 + s * 8) : "memory");
    }
    if (wid == 0)
        asm volatile("tcgen05.alloc.cta_group::1.sync.aligned.shared::cta.b32 [%0], %1;"
                     :: "r"(tslot), "r"(128) : "memory");
    __syncthreads();
    uint32_t tmem;
    asm volatile("ld.shared.b32 %0, [%1];" : "=r"(tmem) : "r"(tslot));

    int npre = (T < 3) ? T : 3;
    for (int c = 0; c < npre; c++) load_chunk(c, c);

    const uint64_t DBASE = (2ull << 61) | (1ull << 46) | (64ull << 32) | (1ull << 16);
    const uint32_t IDESC = (1u << 4) | (1u << 7) | (1u << 10) | ((128u / 8) << 17) | ((128u / 16) << 24);

    for (int c = 0; c < T; c++) {
        int s = c & 3;
        int rem = (T - 1) - c;
        if (rem >= 2)      asm volatile("cp.async.wait_group 2;" ::: "memory");
        else if (rem == 1) asm volatile("cp.async.wait_group 1;" ::: "memory");
        else               asm volatile("cp.async.wait_group 0;" ::: "memory");
        __syncthreads();
        if (wid == 4) {
            asm volatile("fence.proxy.async.shared::cta;" ::: "memory");
            uint32_t pr;
            asm volatile("{ .reg .pred p; elect.sync _|p, 0xFFFFFFFF; selp.b32 %0,1,0,p; }" : "=r"(pr));
            if (pr) {
                uint32_t stA = tiles + s * STAGE_BYTES;
                uint64_t ad = DBASE | ((uint64_t)((stA >> 4) & 0x3FFF));
                uint64_t bd = DBASE | ((uint64_t)(((stA + 16384) >> 4) & 0x3FFF));
                #pragma unroll
                for (int k = 0; k < 4; k++) {
                    uint32_t en = (c == 0 && k == 0) ? 0u : 1u;
                    asm volatile(
                        "{\n\t.reg .pred p;\n\t"
                        "setp.ne.u32 p, %5, 0;\n\t"
                        "tcgen05.mma.cta_group::1.kind::f16 [%0], %1, %2, %3, {%4, %4, %4, %4}, p;\n\t}"
                        :: "r"(tmem), "l"(ad + 2 * k), "l"(bd + 2 * k), "r"(IDESC), "r"(0u), "r"(en)
                        : "memory");
                }
                asm volatile("tcgen05.commit.cta_group::1.mbarrier::arrive::one.shared::cluster.b64 [%0];"
                             :: "r"(mbar0 + s * 8) : "memory");
            }
        }
        int n = c + 3;
        if (n < T) {
            int q = n - 4;
            if (q >= 0) mwait(mbar0 + (q & 3) * 8, (q >> 2) & 1);
            load_chunk(n, n & 3);
        }
    }
    mwait(mbar0 + ((T - 1) & 3) * 8, ((T - 1) >> 2) & 1);
    asm volatile("tcgen05.fence::after_thread_sync;" ::: "memory");

    // epilogue: warp w -> rows (w&3)*32+lane, cols (w>>2)*64 .. +63
    {
        int half = wid >> 2;
        int sub = wid & 3;
        int row = mBase + sub * 32 + lane;
        #pragma unroll
        for (int j = 0; j < 2; j++) {
            int colc = half * 64 + j * 32;
            uint32_t r[32];
            LDTM32(r, tmem + colc);
            asm volatile("tcgen05.wait::ld.sync.aligned;" ::: "memory");
            if (row < P.M) {
                float* cp = P.C + (size_t)row * P.Ncols + nBase + colc;
                const float* bp = P.bias + nBase + colc;
                #pragma unroll
                for (int i = 0; i < 32; i += 4) {
                    float4 v;
                    v.x = __uint_as_float(r[i + 0]) + bp[i + 0];
                    v.y = __uint_as_float(r[i + 1]) + bp[i + 1];
                    v.z = __uint_as_float(r[i + 2]) + bp[i + 2];
                    v.w = __uint_as_float(r[i + 3]) + bp[i + 3];
                    if (P.relu) {
                        v.x = fmaxf(v.x, 0.f); v.y = fmaxf(v.y, 0.f);
                        v.z = fmaxf(v.z, 0.f); v.w = fmaxf(v.w, 0.f);
                    }
                    *(float4*)(cp + i) = v;
                }
            }
        }
    }
    asm volatile("tcgen05.fence::before_thread_sync;" ::: "memory");
    __syncthreads();
    if (wid == 0) {
        asm volatile("tcgen05.relinquish_alloc_permit.cta_group::1.sync.aligned;");
        asm volatile("tcgen05.dealloc.cta_group::1.sync.aligned.b32 %0, %1;" :: "r"(tmem), "r"(128));
    }
#else
    // ================= mma.sync bf16 fallback =================
    // 8 warps, 4(m) x 2(n): warp tile 32(m) x 64(n). mma.m16n8k16.
    int mw = wid >> 1, nw = wid & 1;
    float acc[2][8][4];
    #pragma unroll
    for (int mi = 0; mi < 2; mi++)
        #pragma unroll
        for (int n8 = 0; n8 < 8; n8++)
            #pragma unroll
            for (int q = 0; q < 4; q++) acc[mi][n8][q] = 0.0f;

    int npre = (T < 3) ? T : 3;
    for (int c = 0; c < npre; c++) load_chunk(c, c);

    for (int c = 0; c < T; c++) {
        int s = c & 3;
        int rem = (T - 1) - c;
        if (rem >= 2)      asm volatile("cp.async.wait_group 2;" ::: "memory");
        else if (rem == 1) asm volatile("cp.async.wait_group 1;" ::: "memory");
        else               asm volatile("cp.async.wait_group 0;" ::: "memory");
        __syncthreads();

        uint32_t stA = tiles + s * STAGE_BYTES;
        uint32_t stB = stA + 16384;
        #pragma unroll
        for (int ks = 0; ks < 4; ks++) {
            uint32_t a[2][4];
            uint32_t arow = mw * 32 + ((lane >> 3) & 1) * 8 + (lane & 7);
            uint32_t akb  = ks * 32 + (lane >> 4) * 16;
            #pragma unroll
            for (int mi = 0; mi < 2; mi++) {
                uint32_t ad = stA + swz((arow + mi * 16) * 128 + akb);
                asm volatile("ldmatrix.sync.aligned.m8n8.x4.shared.b16 {%0,%1,%2,%3}, [%4];"
                             : "=r"(a[mi][0]), "=r"(a[mi][1]), "=r"(a[mi][2]), "=r"(a[mi][3])
                             : "r"(ad));
            }
            uint32_t b[4][4];
            uint32_t brow = nw * 64 + ((lane >> 4) & 1) * 8 + (lane & 7);
            uint32_t bkb  = ks * 32 + ((lane >> 3) & 1) * 16;
            #pragma unroll
            for (int ni = 0; ni < 4; ni++) {
                uint32_t bd = stB + swz((brow + ni * 16) * 128 + bkb);
                asm volatile("ldmatrix.sync.aligned.m8n8.x4.shared.b16 {%0,%1,%2,%3}, [%4];"
                             : "=r"(b[ni][0]), "=r"(b[ni][1]), "=r"(b[ni][2]), "=r"(b[ni][3])
                             : "r"(bd));
            }
            #pragma unroll
            for (int mi = 0; mi < 2; mi++)
                #pragma unroll
                for (int n8 = 0; n8 < 8; n8++) {
                    uint32_t b0 = b[n8 >> 1][(n8 & 1) * 2 + 0];
                    uint32_t b1 = b[n8 >> 1][(n8 & 1) * 2 + 1];
                    asm volatile(
                        "mma.sync.aligned.m16n8k16.row.col.f32.bf16.bf16.f32 "
                        "{%0,%1,%2,%3}, {%4,%5,%6,%7}, {%8,%9}, {%0,%1,%2,%3};"
                        : "+f"(acc[mi][n8][0]), "+f"(acc[mi][n8][1]),
                          "+f"(acc[mi][n8][2]), "+f"(acc[mi][n8][3])
                        : "r"(a[mi][0]), "r"(a[mi][1]), "r"(a[mi][2]), "r"(a[mi][3]),
                          "r"(b0), "r"(b1));
                }
        }
        int n = c + 3;
        if (n < T) load_chunk(n, n & 3);
    }

    // epilogue
    {
        int g = lane >> 2, t4 = lane & 3;
        #pragma unroll
        for (int mi = 0; mi < 2; mi++) {
            #pragma unroll
            for (int n8 = 0; n8 < 8; n8++) {
                int col = nBase + nw * 64 + n8 * 8 + t4 * 2;
                float bx = P.bias[col], by = P.bias[col + 1];
                int r0 = mBase + mw * 32 + mi * 16 + g;
                if (r0 < P.M) {
                    float2 v;
                    v.x = acc[mi][n8][0] + bx;
                    v.y = acc[mi][n8][1] + by;
                    if (P.relu) { v.x = fmaxf(v.x, 0.f); v.y = fmaxf(v.y, 0.f); }
                    *(float2*)(P.C + (size_t)r0 * P.Ncols + col) = v;
                }
                int r1 = r0 + 8;
                if (r1 < P.M) {
                    float2 v;
                    v.x = acc[mi][n8][2] + bx;
                    v.y = acc[mi][n8][3] + by;
                    if (P.relu) { v.x = fmaxf(v.x, 0.f); v.y = fmaxf(v.y, 0.f); }
                    *(float2*)(P.C + (size_t)r1 * P.Ncols + col) = v;
                }
            }
        }
    }
#endif
}

// ---------------- BN stats / params / apply ----------------
__global__ void k_colstats(const float* __restrict__ X) {
    int t = threadIdx.x;  // 256
    int rows_per = (N_NODES + gridDim.x - 1) / gridDim.x;
    int r0 = blockIdx.x * rows_per;
    int r1 = min(N_NODES, r0 + rows_per);
    float s[4] = {0, 0, 0, 0}, q[4] = {0, 0, 0, 0};
    for (int r = r0; r < r1; r++) {
        const float* row = X + (size_t)r * HID;
        #pragma unroll
        for (int j = 0; j < 4; j++) {
            float v = row[t + j * 256];
            s[j] += v; q[j] += v * v;
        }
    }
    #pragma unroll
    for (int j = 0; j < 4; j++) {
        atomicAdd(&g_sum[t + j * 256], s[j]);
        atomicAdd(&g_sumsq[t + j * 256], q[j]);
    }
}
__global__ void k_bnparams(const float* __restrict__ g, const float* __restrict__ be) {
    int c = blockIdx.x * blockDim.x + threadIdx.x;
    if (c < HID) {
        float m = g_sum[c] * (1.0f / N_NODES);
        float var = g_sumsq[c] * (1.0f / N_NODES) - m * m;
        float a = g[c] * rsqrtf(var + EPS_BN);
        g_a[c] = a;
        g_c[c] = be[c] - m * a;
    }
}
__global__ void k_bnrelu(const float* __restrict__ X, float* __restrict__ Y,
                         __nv_bfloat16* __restrict__ YH, __nv_bfloat16* __restrict__ YL) {
    size_t i = (size_t)blockIdx.x * blockDim.x + threadIdx.x;
    const size_t total = (size_t)N_NODES * HID / 4;
    if (i < total) {
        int c = (int)((i * 4) % HID);
        float4 v = ((const float4*)X)[i];
        v.x = fmaxf(0.f, v.x * g_a[c + 0] + g_c[c + 0]);
        v.y = fmaxf(0.f, v.y * g_a[c + 1] + g_c[c + 1]);
        v.z = fmaxf(0.f, v.z * g_a[c + 2] + g_c[c + 2]);
        v.w = fmaxf(0.f, v.w * g_a[c + 3] + g_c[c + 3]);
        ((float4*)Y)[i] = v;
        __nv_bfloat16 hx = __float2bfloat16(v.x), hy = __float2bfloat16(v.y);
        __nv_bfloat16 hz = __float2bfloat16(v.z), hw = __float2bfloat16(v.w);
        __nv_bfloat162* H2 = (__nv_bfloat162*)YH;
        __nv_bfloat162* L2 = (__nv_bfloat162*)YL;
        H2[i * 2 + 0] = __nv_bfloat162(hx, hy);
        H2[i * 2 + 1] = __nv_bfloat162(hz, hw);
        L2[i * 2 + 0] = __nv_bfloat162(__float2bfloat16(v.x - __bfloat162float(hx)),
                                       __float2bfloat16(v.y - __bfloat162float(hy)));
        L2[i * 2 + 1] = __nv_bfloat162(__float2bfloat16(v.z - __bfloat162float(hz)),
                                       __float2bfloat16(v.w - __bfloat162float(hw)));
    }
}

// ---------------- final head ----------------
__global__ void k_out(const float* __restrict__ H, const float* __restrict__ Wo,
                      const float* __restrict__ bo, float* __restrict__ Out) {
    __shared__ float sw[F_MID * N_OUT];
    for (int i = threadIdx.x; i < F_MID * N_OUT; i += blockDim.x) sw[i] = Wo[i];
    __syncthreads();
    int warp = threadIdx.x / 32, lane = threadIdx.x % 32;
    int row = blockIdx.x * (blockDim.x / 32) + warp;
    if (row >= N_NODES) return;
    float acc[N_OUT];
    #pragma unroll
    for (int o = 0; o < N_OUT; o++) acc[o] = 0.0f;
    const float* h = H + (size_t)row * F_MID;
    for (int k = lane; k < F_MID; k += 32) {
        float hv = h[k];
        #pragma unroll
        for (int o = 0; o < N_OUT; o++) acc[o] += hv * sw[k * N_OUT + o];
    }
    #pragma unroll
    for (int o = 0; o < N_OUT; o++)
        #pragma unroll
        for (int off = 16; off; off >>= 1)
            acc[o] += __shfl_down_sync(0xffffffffu, acc[o], off);
    if (lane == 0)
        #pragma unroll
        for (int o = 0; o < N_OUT; o++)
            Out[(size_t)row * N_OUT + o] = acc[o] + bo[o];
}

// ---------------- host-side GEMM launcher ----------------
struct PassDef { const __nv_bfloat16* A; const __nv_bfloat16* B; int Kw; };
static void run_gemm(const PassDef* passes, int np, const float* bias, float* C,
                     int M, int N, int relu) {
    GemmParams P = {};
    int cum = 0;
    for (int i = 0; i < np; i++) {
        P.A[i] = passes[i].A;
        P.B[i] = passes[i].B;
        P.Kw[i] = passes[i].Kw;
        cum += passes[i].Kw / 64;
        P.chEnd[i] = cum;
    }
    P.totalChunks = cum;
    P.bias = bias; P.C = C; P.M = M; P.Ncols = N; P.relu = relu;
    dim3 g((M + 127) / 128, N / 128);
    k_gemm<<<g, 256, SMEM_REQ>>>(P);
}

// ---------------- launch ----------------
extern "C" void kernel_launch(void* const* d_in, const int* in_sizes, int n_in,
                              void* d_out, int out_size) {
    const float* x   = (const float*)d_in[0];
    const void*  edges = d_in[1];
    const float* W1l = (const float*)d_in[2];
    const float* b1  = (const float*)d_in[3];
    const float* W1r = (const float*)d_in[4];
    const float* g1  = (const float*)d_in[5];
    const float* be1 = (const float*)d_in[6];
    const float* W2l = (const float*)d_in[7];
    const float* b2  = (const float*)d_in[8];
    const float* W2r = (const float*)d_in[9];
    const float* g2  = (const float*)d_in[10];
    const float* be2 = (const float*)d_in[11];
    const float* Wf  = (const float*)d_in[12];
    const float* bf  = (const float*)d_in[13];
    const float* Wo  = (const float*)d_in[14];
    const float* bo  = (const float*)d_in[15];
    float* out = (float*)d_out;

    cudaFuncSetAttribute(k_gemm, cudaFuncAttributeMaxDynamicSharedMemorySize, SMEM_REQ);

    void *p_deg, *p_sum, *p_sumsq, *p_tmp, *p_h, *p_Ah, *p_Al, *p_Bh, *p_Bl, *p_Wh, *p_Wl;
    cudaGetSymbolAddress(&p_deg, g_deg);
    cudaGetSymbolAddress(&p_sum, g_sum);
    cudaGetSymbolAddress(&p_sumsq, g_sumsq);
    cudaGetSymbolAddress(&p_tmp, g_tmp);
    cudaGetSymbolAddress(&p_h, g_h);
    cudaGetSymbolAddress(&p_Ah, g_Ah);
    cudaGetSymbolAddress(&p_Al, g_Al);
    cudaGetSymbolAddress(&p_Bh, g_Bh);
    cudaGetSymbolAddress(&p_Bl, g_Bl);
    cudaGetSymbolAddress(&p_Wh, g_Wh);
    cudaGetSymbolAddress(&p_Wl, g_Wl);
    float* tmp = (float*)p_tmp;
    float* h   = (float*)p_h;
    __nv_bfloat16* Ah = (__nv_bfloat16*)p_Ah;
    __nv_bfloat16* Al = (__nv_bfloat16*)p_Al;
    __nv_bfloat16* Bh = (__nv_bfloat16*)p_Bh;
    __nv_bfloat16* Bl = (__nv_bfloat16*)p_Bl;
    __nv_bfloat16* Wh = (__nv_bfloat16*)p_Wh;
    __nv_bfloat16* Wl = (__nv_bfloat16*)p_Wl;

    // CSR build
    cudaMemsetAsync(p_deg, 0, N_NODES * sizeof(int));
    k_detect<<<1, 32>>>((const unsigned int*)edges);
    k_hist<<<(N_EDGES + 255) / 256, 256>>>(edges);
    k_scan<<<1, 1024>>>();
    k_scatter<<<(N_EDGES + 255) / 256, 256>>>(edges);

    // weight transpose + split
    dim3 wb(32, 8);
    k_wt<<<dim3(F_IN / 32, HID / 32), wb>>>(W1l, Wh + OFF_W1L, Wl + OFF_W1L, F_IN, HID);
    k_wt<<<dim3(F_IN / 32, HID / 32), wb>>>(W1r, Wh + OFF_W1R, Wl + OFF_W1R, F_IN, HID);
    k_wt<<<dim3(HID / 32, HID / 32), wb>>>(W2l, Wh + OFF_W2L, Wl + OFF_W2L, HID, HID);
    k_wt<<<dim3(HID / 32, HID / 32), wb>>>(W2r, Wh + OFF_W2R, Wl + OFF_W2R, HID, HID);
    k_wt<<<dim3(HID / 32, F_MID / 32), wb>>>(Wf, Wh + OFF_WF, Wl + OFF_WF, HID, F_MID);

    // x split
    {
        size_t n = (size_t)N_NODES * F_IN;
        k_split<<<(unsigned)((n + 255) / 256), 256>>>(x, Bh, Bl, n);
    }

    // ---- layer 1 ----
    k_aggregate<F_IN><<<N_NODES, 128>>>(x, Ah, Al);
    {
        PassDef pl[6] = {
            {Ah, Wh + OFF_W1L, F_IN}, {Ah, Wl + OFF_W1L, F_IN}, {Al, Wh + OFF_W1L, F_IN},
            {Bh, Wh + OFF_W1R, F_IN}, {Bh, Wl + OFF_W1R, F_IN}, {Bl, Wh + OFF_W1R, F_IN},
        };
        run_gemm(pl, 6, b1, tmp, N_NODES, HID, 0);
    }
    cudaMemsetAsync(p_sum, 0, HID * sizeof(float));
    cudaMemsetAsync(p_sumsq, 0, HID * sizeof(float));
    k_colstats<<<128, 256>>>(tmp);
    k_bnparams<<<HID / 256, 256>>>(g1, be1);
    {
        size_t n4 = (size_t)N_NODES * HID / 4;
        k_bnrelu<<<(unsigned)((n4 + 255) / 256), 256>>>(tmp, h, Bh, Bl);
    }

    // ---- layer 2 ----
    k_aggregate<HID><<<N_NODES, 128>>>(h, Ah, Al);
    {
        PassDef pl[6] = {
            {Ah, Wh + OFF_W2L, HID}, {Ah, Wl + OFF_W2L, HID}, {Al, Wh + OFF_W2L, HID},
            {Bh, Wh + OFF_W2R, HID}, {Bh, Wl + OFF_W2R, HID}, {Bl, Wh + OFF_W2R, HID},
        };
        run_gemm(pl, 6, b2, tmp, N_NODES, HID, 0);
    }
    cudaMemsetAsync(p_sum, 0, HID * sizeof(float));
    cudaMemsetAsync(p_sumsq, 0, HID * sizeof(float));
    k_colstats<<<128, 256>>>(tmp);
    k_bnparams<<<HID / 256, 256>>>(g2, be2);
    {
        size_t n4 = (size_t)N_NODES * HID / 4;
        k_bnrelu<<<(unsigned)((n4 + 255) / 256), 256>>>(tmp, h, Bh, Bl);
    }

    // ---- fc + ReLU ----
    {
        PassDef pl[3] = {
            {Bh, Wh + OFF_WF, HID}, {Bh, Wl + OFF_WF, HID}, {Bl, Wh + OFF_WF, HID},
        };
        run_gemm(pl, 3, bf, tmp, N_NODES, F_MID, 1);
    }

    // ---- head ----
    k_out<<<(N_NODES + 7) / 8, 256>>>(tmp, Wo, bo, out);
}